// round 3
// baseline (speedup 1.0000x reference)
#include <cuda_runtime.h>
#include <math.h>

#define NB 8
#define CIN 32
#define DIN 16
#define COUT 64
#define HOUT 63

typedef unsigned long long ull;

// ---- scratch ----
__device__ __align__(16) float g_XP[NB * 96 * 1024 + 64];   // [b][c96][hi*32+wi] (+pad)
__device__ __align__(16) float g_Wc2[96 * 576 * 2];          // [c96][kh][kw][co][2] duplicated

// classes (heavy first): 0=oo(K=384) 1=oe(192) 2=eo(192) 3=ee(96)
__constant__ int c_dlt[4][4]  = {{33,32,1,0},{32,0,0,0},{1,0,0,0},{0,0,0,0}};
__constant__ int c_wofs[4][4] = {{0,256,768,1024},{128,896,0,0},{384,640,0,0},{512,0,0,0}};
__constant__ int c_nt[4] = {24, 12, 12, 6};   // k-tiles of 16 (K/16)
__constant__ int c_oh[4] = {1, 1, 0, 0};
__constant__ int c_ow[4] = {1, 0, 1, 0};

// ---------------- prep: pack XP = [sum_d x ; x[d=0] ; x[d=15]] (single pass) ----------------
__global__ void __launch_bounds__(256)
prep_x_kernel(const float* __restrict__ x) {
    int i = blockIdx.x * 256 + threadIdx.x;      // 0 .. 8*32*256-1 (float4 granules)
    int q  = i & 255;
    int bc = i >> 8;                              // b*32+ci
    int b  = bc >> 5, ci = bc & 31;
    const float4* p = (const float4*)x + (size_t)bc * (DIN * 256) + q;
    float4 d0 = p[0];
    float4 s = d0;
    float4 d15;
#pragma unroll
    for (int d = 1; d < DIN; d++) {
        float4 v = p[d * 256];
        s.x += v.x; s.y += v.y; s.z += v.z; s.w += v.w;
        if (d == DIN - 1) d15 = v;
    }
    float4* xp4 = (float4*)g_XP;
    xp4[((size_t)b * 96 + ci) * 256 + q]      = s;
    xp4[((size_t)b * 96 + 32 + ci) * 256 + q] = d0;
    xp4[((size_t)b * 96 + 64 + ci) * 256 + q] = d15;
}

// ---------------- prep: combine weights over kd, duplicated for f32x2 ----------------
__global__ void wc_kernel(const float* __restrict__ w) {
    int i = blockIdx.x * blockDim.x + threadIdx.x;
    if (i >= 96 * 576) return;
    int co = i & 63;
    int kw = (i >> 6) % 3;
    int kh = (i / 192) % 3;
    int c96 = i / 576;
    int s = c96 >> 5;
    int ci = c96 & 31;
    int base = (ci * 64 + co) * 27 + kh * 3 + kw;
    float v;
    if (s == 0)      v = w[base] + w[base + 9] + w[base + 18];
    else if (s == 1) v = -w[base];
    else             v = -w[base + 18];
    *(float2*)&g_Wc2[(size_t)i * 2] = make_float2(v, v);
}

#define FMA2(d, a, b) asm("fma.rn.f32x2 %0, %1, %2, %3;" : "=l"(d) : "l"(a), "l"(b), "l"(d))

// ---------------- fused GEMM + softmax + tanh ----------------
// grid 256: cls=bid>>6 (heavy first), b=(bid>>3)&7, mt=bid&7. Block tile 128m x 64n, KT=16.
// 256 threads: n0=(tid&15)*4, m0=(tid>>4)*8. Thread tile 8m x 4n via FFMA2.
__global__ void __launch_bounds__(256, 2)
gemm_fused(const float* __restrict__ conv_bias,
           const float* __restrict__ bias,
           float* __restrict__ out) {
    __shared__ float sA[16 * 128];
    __shared__ float sB[16 * 128];
    __shared__ float s_cb[COUT];

    const int tid = threadIdx.x;
    const int bid = blockIdx.x;
    const int cls = bid >> 6;
    const int b   = (bid >> 3) & 7;
    const int mt  = bid & 7;
    const int mbase = mt * 128;
    const int ntiles = c_nt[cls];
    const float* __restrict__ xpb = g_XP + (size_t)b * 96 * 1024;

    if (tid < COUT) s_cb[tid] = conv_bias[tid] + bias[tid];

    const int n0 = (tid & 15) << 2;
    const int m0 = (tid >> 4) << 3;

    ull acc[16];
#pragma unroll
    for (int i = 0; i < 16; i++) acc[i] = 0ull;

    float  rA[8];
    float4 rB[2];

    // prefetch tile 0
    {
        const int dlt = c_dlt[cls][0];
        const int wofs = c_wofs[cls][0];
#pragma unroll
        for (int l = 0; l < 8; l++) {
            int flat = tid + l * 256;
            int kr = flat >> 7, col = flat & 127;
            rA[l] = __ldg(&xpb[kr * 1024 + mbase + col + dlt]);
        }
#pragma unroll
        for (int l = 0; l < 2; l++) {
            int f4 = tid + l * 256;
            int kr = f4 >> 5, c4 = f4 & 31;
            rB[l] = *(const float4*)&g_Wc2[(size_t)kr * 1152 + wofs + c4 * 4];
        }
    }

    for (int t = 0; t < ntiles; t++) {
        __syncthreads();
#pragma unroll
        for (int l = 0; l < 8; l++) sA[tid + l * 256] = rA[l];
#pragma unroll
        for (int l = 0; l < 2; l++) *(float4*)&sB[(tid + l * 256) * 4] = rB[l];
        __syncthreads();

        if (t + 1 < ntiles) {
            const int tn = t + 1;
            const int j = tn / 6;
            const int c96b = (tn - j * 6) * 16;
            const int dlt = c_dlt[cls][j];
            const int wofs = c_wofs[cls][j];
#pragma unroll
            for (int l = 0; l < 8; l++) {
                int flat = tid + l * 256;
                int kr = flat >> 7, col = flat & 127;
                rA[l] = __ldg(&xpb[(c96b + kr) * 1024 + mbase + col + dlt]);
            }
#pragma unroll
            for (int l = 0; l < 2; l++) {
                int f4 = tid + l * 256;
                int kr = f4 >> 5, c4 = f4 & 31;
                rB[l] = *(const float4*)&g_Wc2[(size_t)(c96b + kr) * 1152 + wofs + c4 * 4];
            }
        }

#pragma unroll
        for (int kk = 0; kk < 16; kk++) {
            ulonglong2 a01 = *(const ulonglong2*)&sA[kk * 128 + m0];
            ulonglong2 a23 = *(const ulonglong2*)&sA[kk * 128 + m0 + 4];
            ulonglong2 b01 = *(const ulonglong2*)&sB[kk * 128 + n0 * 2];
            ulonglong2 b23 = *(const ulonglong2*)&sB[kk * 128 + n0 * 2 + 4];
            FMA2(acc[0],  a01.x, b01.x); FMA2(acc[1],  a01.x, b01.y);
            FMA2(acc[2],  a01.x, b23.x); FMA2(acc[3],  a01.x, b23.y);
            FMA2(acc[4],  a01.y, b01.x); FMA2(acc[5],  a01.y, b01.y);
            FMA2(acc[6],  a01.y, b23.x); FMA2(acc[7],  a01.y, b23.y);
            FMA2(acc[8],  a23.x, b01.x); FMA2(acc[9],  a23.x, b01.y);
            FMA2(acc[10], a23.x, b23.x); FMA2(acc[11], a23.x, b23.y);
            FMA2(acc[12], a23.y, b01.x); FMA2(acc[13], a23.y, b01.y);
            FMA2(acc[14], a23.y, b23.x); FMA2(acc[15], a23.y, b23.y);
        }
    }

    // ---- fused epilogue: mean-scale + biases + channel softmax + tanh*2 ----
    float vv[8][4];
#pragma unroll
    for (int i = 0; i < 4; i++)
#pragma unroll
        for (int j = 0; j < 4; j++) {
            ull v = acc[i * 4 + j];
            vv[2 * i][j]     = __uint_as_float((unsigned)(v & 0xFFFFFFFFull));
            vv[2 * i + 1][j] = __uint_as_float((unsigned)(v >> 32));
        }

    const float inv_d = 1.0f / 31.0f;
    float cbs[4];
#pragma unroll
    for (int j = 0; j < 4; j++) cbs[j] = s_cb[n0 + j];
    const int oh = c_oh[cls], ow = c_ow[cls];

#pragma unroll
    for (int mi = 0; mi < 8; mi++) {
        float t0 = vv[mi][0] * inv_d + cbs[0];
        float t1 = vv[mi][1] * inv_d + cbs[1];
        float t2 = vv[mi][2] * inv_d + cbs[2];
        float t3 = vv[mi][3] * inv_d + cbs[3];
        float mx = fmaxf(fmaxf(t0, t1), fmaxf(t2, t3));
#pragma unroll
        for (int o = 1; o <= 8; o <<= 1)
            mx = fmaxf(mx, __shfl_xor_sync(0xffffffffu, mx, o));
        float e0 = __expf(t0 - mx), e1 = __expf(t1 - mx);
        float e2 = __expf(t2 - mx), e3 = __expf(t3 - mx);
        float sum = (e0 + e1) + (e2 + e3);
#pragma unroll
        for (int o = 1; o <= 8; o <<= 1)
            sum += __shfl_xor_sync(0xffffffffu, sum, o);
        float rs = 1.0f / sum;

        int m = mbase + m0 + mi;
        int hq = m >> 5, wq = m & 31;
        int ho = 2 * hq + oh, wo = 2 * wq + ow;
        if (ho < HOUT && wo < HOUT) {
            size_t pix = (size_t)ho * HOUT + wo;
            float e[4] = {e0, e1, e2, e3};
#pragma unroll
            for (int j = 0; j < 4; j++) {
                float s = e[j] * rs;
                float tt = __expf(-2.0f * s);
                float r = __fdividef(4.0f, 1.0f + tt) - 2.0f;   // 2*tanh(s)
                out[((size_t)(b * COUT + n0 + j)) * (HOUT * HOUT) + pix] = r;
            }
        }
    }
}

extern "C" void kernel_launch(void* const* d_in, const int* in_sizes, int n_in,
                              void* d_out, int out_size) {
    (void)in_sizes; (void)n_in; (void)out_size;
    const float* x         = (const float*)d_in[0];
    const float* w         = (const float*)d_in[1];
    const float* conv_bias = (const float*)d_in[2];
    const float* bias      = (const float*)d_in[3];
    float* out             = (float*)d_out;

    prep_x_kernel<<<(NB * CIN * 256) / 256, 256>>>(x);
    wc_kernel<<<(96 * 576 + 255) / 256, 256>>>(w);
    gemm_fused<<<256, 256>>>(conv_bias, bias, out);
}

// round 4
// speedup vs baseline: 1.6286x; 1.6286x over previous
#include <cuda_runtime.h>
#include <math.h>

#define NB 8
#define CIN 32
#define DIN 16
#define COUT 64
#define HOUT 63

// ---- scratch (device globals; no cudaMalloc allowed) ----
__device__ __align__(16) float g_XP[NB * 96 * 1024 + 64];   // [b][c96][hi*32+wi] (+pad)
__device__ __align__(16) float g_Wc[96 * 576];               // [c96][kh][kw][co]

// classes (heavy first): 0=oo(K=384) 1=oe(192) 2=eo(192) 3=ee(96)
__constant__ int c_dlt[4][4]  = {{33,32,1,0},{32,0,0,0},{1,0,0,0},{0,0,0,0}};
// weight row offset within a c96 row: kh*192 + kw*64
__constant__ int c_wofs[4][4] = {{0,128,384,512},{64,448,0,0},{192,320,0,0},{256,0,0,0}};
__constant__ int c_nt[4] = {12, 6, 6, 3};   // K/32
__constant__ int c_oh[4] = {1, 1, 0, 0};
__constant__ int c_ow[4] = {1, 0, 1, 0};

// ---------------- prep: pack XP = [sum_d x ; x[d=0] ; x[d=15]] (single pass) ----------------
__global__ void __launch_bounds__(256)
prep_x_kernel(const float* __restrict__ x) {
    int i = blockIdx.x * 256 + threadIdx.x;      // 0 .. 8*32*512-1 (float2 granules)
    int q  = i & 511;
    int bc = i >> 9;                              // b*32+ci
    int b  = bc >> 5, ci = bc & 31;
    const float2* p = (const float2*)x + (size_t)bc * (DIN * 512) + q;
    float2 d0 = p[0];
    float2 s = d0;
    float2 d15;
#pragma unroll
    for (int d = 1; d < DIN; d++) {
        float2 v = p[d * 512];
        s.x += v.x; s.y += v.y;
        if (d == DIN - 1) d15 = v;
    }
    float2* xp2 = (float2*)g_XP;
    xp2[((size_t)b * 96 + ci) * 512 + q]      = s;
    xp2[((size_t)b * 96 + 32 + ci) * 512 + q] = d0;
    xp2[((size_t)b * 96 + 64 + ci) * 512 + q] = d15;
}

// ---------------- prep: combine weights over kd ----------------
// w layout: (ci, co, kd, kh, kw); c96 = s*32+ci; s0: sum_kd; s1: -w[kd=0]; s2: -w[kd=2]
__global__ void wc_kernel(const float* __restrict__ w) {
    int i = blockIdx.x * blockDim.x + threadIdx.x;
    if (i >= 96 * 576) return;
    int co = i & 63;
    int kw = (i >> 6) % 3;
    int kh = (i / 192) % 3;
    int c96 = i / 576;
    int s = c96 >> 5;
    int ci = c96 & 31;
    int base = (ci * 64 + co) * 27 + kh * 3 + kw;
    float v;
    if (s == 0)      v = w[base] + w[base + 9] + w[base + 18];
    else if (s == 1) v = -w[base];
    else             v = -w[base + 18];
    g_Wc[i] = v;
}

// ---------------- fused GEMM + mean + biases + softmax + tanh ----------------
// grid 512: cls=bid>>7 (heavy first), b=(bid>>4)&7, mt=bid&15. Block tile 64m x 64n, KT=32.
// 256 threads: n0=(tid&15)*4, m0=(tid>>4)*4. Thread tile 4m x 4n scalar FFMA.
#define KT 32
#define MT 64
__global__ void __launch_bounds__(256, 3)
gemm_fused(const float* __restrict__ conv_bias,
           const float* __restrict__ bias,
           float* __restrict__ out) {
    __shared__ float sA[KT * MT];   // [k][m]
    __shared__ float sB[KT * 64];   // [k][n]
    __shared__ float s_cb[COUT];

    const int tid = threadIdx.x;
    const int bid = blockIdx.x;
    const int cls = bid >> 7;
    const int b   = (bid >> 4) & 7;
    const int mt  = bid & 15;
    const int mbase = mt * MT;
    const int ntiles = c_nt[cls];
    const float* __restrict__ xpb = g_XP + (size_t)b * 96 * 1024;

    if (tid < COUT) s_cb[tid] = conv_bias[tid] + bias[tid];

    const int n0 = (tid & 15) << 2;
    const int m0 = (tid >> 4) << 2;

    float acc[16];
#pragma unroll
    for (int i = 0; i < 16; i++) acc[i] = 0.f;

    float  rA[8];
    float4 rB[2];

    // prefetch tile 0 (j=0, c96b=0)
    {
        const int dlt  = c_dlt[cls][0];
        const int wofs = c_wofs[cls][0];
#pragma unroll
        for (int l = 0; l < 8; l++) {
            int flat = tid + l * 256;
            int kr = flat >> 6, col = flat & 63;
            rA[l] = __ldg(&xpb[kr * 1024 + mbase + col + dlt]);
        }
#pragma unroll
        for (int l = 0; l < 2; l++) {
            int f4 = tid + l * 256;
            int kr = f4 >> 4, n4 = f4 & 15;
            rB[l] = *(const float4*)&g_Wc[(size_t)kr * 576 + wofs + n4 * 4];
        }
    }

    for (int t = 0; t < ntiles; t++) {
        __syncthreads();
#pragma unroll
        for (int l = 0; l < 8; l++) sA[tid + l * 256] = rA[l];
#pragma unroll
        for (int l = 0; l < 2; l++) {
            int f4 = tid + l * 256;
            *(float4*)&sB[f4 * 4] = rB[l];
        }
        __syncthreads();

        if (t + 1 < ntiles) {
            const int tn = t + 1;
            const int j = tn / 3;                 // 3 tiles of 32 per 96-k plane
            const int c96b = (tn - j * 3) * KT;
            const int dlt  = c_dlt[cls][j];
            const int wofs = c_wofs[cls][j];
#pragma unroll
            for (int l = 0; l < 8; l++) {
                int flat = tid + l * 256;
                int kr = flat >> 6, col = flat & 63;
                rA[l] = __ldg(&xpb[(c96b + kr) * 1024 + mbase + col + dlt]);
            }
#pragma unroll
            for (int l = 0; l < 2; l++) {
                int f4 = tid + l * 256;
                int kr = f4 >> 4, n4 = f4 & 15;
                rB[l] = *(const float4*)&g_Wc[(size_t)(c96b + kr) * 576 + wofs + n4 * 4];
            }
        }

#pragma unroll
        for (int kk = 0; kk < KT; kk++) {
            float4 a  = *(const float4*)&sA[kk * MT + m0];
            float4 bb = *(const float4*)&sB[kk * 64 + n0];
            acc[0]  = fmaf(a.x, bb.x, acc[0]);
            acc[1]  = fmaf(a.x, bb.y, acc[1]);
            acc[2]  = fmaf(a.x, bb.z, acc[2]);
            acc[3]  = fmaf(a.x, bb.w, acc[3]);
            acc[4]  = fmaf(a.y, bb.x, acc[4]);
            acc[5]  = fmaf(a.y, bb.y, acc[5]);
            acc[6]  = fmaf(a.y, bb.z, acc[6]);
            acc[7]  = fmaf(a.y, bb.w, acc[7]);
            acc[8]  = fmaf(a.z, bb.x, acc[8]);
            acc[9]  = fmaf(a.z, bb.y, acc[9]);
            acc[10] = fmaf(a.z, bb.z, acc[10]);
            acc[11] = fmaf(a.z, bb.w, acc[11]);
            acc[12] = fmaf(a.w, bb.x, acc[12]);
            acc[13] = fmaf(a.w, bb.y, acc[13]);
            acc[14] = fmaf(a.w, bb.z, acc[14]);
            acc[15] = fmaf(a.w, bb.w, acc[15]);
        }
    }

    // ---- fused epilogue: mean-scale + biases + channel softmax + 2*tanh ----
    const float inv_d = 1.0f / 31.0f;
    float cbs[4];
#pragma unroll
    for (int j = 0; j < 4; j++) cbs[j] = s_cb[n0 + j];
    const int oh = c_oh[cls], ow = c_ow[cls];

#pragma unroll
    for (int mi = 0; mi < 4; mi++) {
        float t0 = acc[mi * 4 + 0] * inv_d + cbs[0];
        float t1 = acc[mi * 4 + 1] * inv_d + cbs[1];
        float t2 = acc[mi * 4 + 2] * inv_d + cbs[2];
        float t3 = acc[mi * 4 + 3] * inv_d + cbs[3];
        float mx = fmaxf(fmaxf(t0, t1), fmaxf(t2, t3));
#pragma unroll
        for (int o = 1; o <= 8; o <<= 1)
            mx = fmaxf(mx, __shfl_xor_sync(0xffffffffu, mx, o));
        float e0 = __expf(t0 - mx), e1 = __expf(t1 - mx);
        float e2 = __expf(t2 - mx), e3 = __expf(t3 - mx);
        float sum = (e0 + e1) + (e2 + e3);
#pragma unroll
        for (int o = 1; o <= 8; o <<= 1)
            sum += __shfl_xor_sync(0xffffffffu, sum, o);
        float rs = 1.0f / sum;

        int m = mbase + m0 + mi;
        int hq = m >> 5, wq = m & 31;
        int ho = 2 * hq + oh, wo = 2 * wq + ow;
        if (ho < HOUT && wo < HOUT) {
            size_t pix = (size_t)ho * HOUT + wo;
            float e[4] = {e0, e1, e2, e3};
#pragma unroll
            for (int j = 0; j < 4; j++) {
                float s = e[j] * rs;
                float tt = __expf(-2.0f * s);
                float r = __fdividef(4.0f, 1.0f + tt) - 2.0f;   // 2*tanh(s)
                out[((size_t)(b * COUT + n0 + j)) * (HOUT * HOUT) + pix] = r;
            }
        }
    }
}

extern "C" void kernel_launch(void* const* d_in, const int* in_sizes, int n_in,
                              void* d_out, int out_size) {
    (void)in_sizes; (void)n_in; (void)out_size;
    const float* x         = (const float*)d_in[0];
    const float* w         = (const float*)d_in[1];
    const float* conv_bias = (const float*)d_in[2];
    const float* bias      = (const float*)d_in[3];
    float* out             = (float*)d_out;

    prep_x_kernel<<<(NB * CIN * 512) / 256, 256>>>(x);
    wc_kernel<<<(96 * 576 + 255) / 256, 256>>>(w);
    gemm_fused<<<512, 256>>>(conv_bias, bias, out);
}

// round 5
// speedup vs baseline: 1.6478x; 1.0118x over previous
#include <cuda_runtime.h>
#include <math.h>

#define NB 8
#define CIN 32
#define DIN 16
#define COUT 64
#define HOUT 63

// ---- scratch (device globals; no cudaMalloc allowed) ----
__device__ __align__(16) float g_XP[NB * 96 * 1024 + 64];   // [b][c96][hi*32+wi] (+pad)
__device__ __align__(16) float g_Wc[96 * 576];               // [c96][kh][kw][co]

// classes (heavy first): 0=oo(K=384) 1=oe(192) 2=eo(192) 3=ee(96)
__constant__ int c_dlt[4][4]  = {{33,32,1,0},{32,0,0,0},{1,0,0,0},{0,0,0,0}};
// weight row offset within a c96 row: kh*192 + kw*64
__constant__ int c_wofs[4][4] = {{0,128,384,512},{64,448,0,0},{192,320,0,0},{256,0,0,0}};
__constant__ int c_nt[4] = {12, 6, 6, 3};   // K/32
__constant__ int c_oh[4] = {1, 1, 0, 0};
__constant__ int c_ow[4] = {1, 0, 1, 0};

// ---------------- prep: pack XP = [sum_d x ; x[d=0] ; x[d=15]] (single pass) ----------------
// float4 granules: 256 per (b,ci). 512 blocks x 128 threads.
__global__ void __launch_bounds__(128)
prep_x_kernel(const float* __restrict__ x) {
    int i = blockIdx.x * 128 + threadIdx.x;      // 0 .. 8*32*256-1
    int q  = i & 255;
    int bc = i >> 8;                              // b*32+ci
    int b  = bc >> 5, ci = bc & 31;
    const float4* p = (const float4*)x + (size_t)bc * (DIN * 256) + q;
    float4 d0 = p[0];
    float4 s = d0;
    float4 d15;
#pragma unroll
    for (int d = 1; d < DIN; d++) {
        float4 v = p[d * 256];
        s.x += v.x; s.y += v.y; s.z += v.z; s.w += v.w;
        if (d == DIN - 1) d15 = v;
    }
    float4* xp4 = (float4*)g_XP;
    xp4[((size_t)b * 96 + ci) * 256 + q]      = s;
    xp4[((size_t)b * 96 + 32 + ci) * 256 + q] = d0;
    xp4[((size_t)b * 96 + 64 + ci) * 256 + q] = d15;
}

// ---------------- prep: combine weights over kd ----------------
__global__ void wc_kernel(const float* __restrict__ w) {
    int i = blockIdx.x * blockDim.x + threadIdx.x;
    if (i >= 96 * 576) return;
    int co = i & 63;
    int kw = (i >> 6) % 3;
    int kh = (i / 192) % 3;
    int c96 = i / 576;
    int s = c96 >> 5;
    int ci = c96 & 31;
    int base = (ci * 64 + co) * 27 + kh * 3 + kw;
    float v;
    if (s == 0)      v = w[base] + w[base + 9] + w[base + 18];
    else if (s == 1) v = -w[base];
    else             v = -w[base + 18];
    g_Wc[i] = v;
}

// ---------------- fused GEMM + mean + biases + softmax + tanh ----------------
// grid 512: cls=bid>>7 (heavy first), b=(bid>>4)&7, mt=bid&15. Block 64m x 64n, KT=32.
// 256 threads: n0=(tid&15)*4, m0=(tid>>4)*4. 4x4 thread tile, double-buffered smem.
#define KT 32
#define MT 64
__global__ void __launch_bounds__(256, 3)
gemm_fused(const float* __restrict__ conv_bias,
           const float* __restrict__ bias,
           float* __restrict__ out) {
    __shared__ float sA[2][KT * MT];   // [buf][k][m]
    __shared__ float sB[2][KT * 64];   // [buf][k][n]
    __shared__ float s_cb[COUT];

    const int tid = threadIdx.x;
    const int bid = blockIdx.x;
    const int cls = bid >> 7;
    const int b   = (bid >> 4) & 7;
    const int mt  = bid & 15;
    const int mbase = mt * MT;
    const int ntiles = c_nt[cls];
    const float* __restrict__ xpb = g_XP + (size_t)b * 96 * 1024;

    if (tid < COUT) s_cb[tid] = conv_bias[tid] + bias[tid];

    const int n0 = (tid & 15) << 2;
    const int m0 = (tid >> 4) << 2;

    float acc[16];
#pragma unroll
    for (int i = 0; i < 16; i++) acc[i] = 0.f;

    float  rA[8];
    float4 rB[2];

    // prefetch tile 0 (j=0, c96b=0)
    {
        const int dlt  = c_dlt[cls][0];
        const int wofs = c_wofs[cls][0];
#pragma unroll
        for (int l = 0; l < 8; l++) {
            int flat = tid + l * 256;
            int kr = flat >> 6, col = flat & 63;
            rA[l] = __ldg(&xpb[kr * 1024 + mbase + col + dlt]);
        }
#pragma unroll
        for (int l = 0; l < 2; l++) {
            int f4 = tid + l * 256;
            int kr = f4 >> 4, n4 = f4 & 15;
            rB[l] = *(const float4*)&g_Wc[(size_t)kr * 576 + wofs + n4 * 4];
        }
    }

    for (int t = 0; t < ntiles; t++) {
        const int buf = t & 1;
        // stage current tile into smem buffer `buf`
#pragma unroll
        for (int l = 0; l < 8; l++) sA[buf][tid + l * 256] = rA[l];
#pragma unroll
        for (int l = 0; l < 2; l++) *(float4*)&sB[buf][(tid + l * 256) * 4] = rB[l];
        __syncthreads();

        // issue prefetch for tile t+1 (overlaps with compute below)
        if (t + 1 < ntiles) {
            const int tn = t + 1;
            const int j = tn / 3;                 // 3 tiles of 32 per 96-k plane
            const int c96b = (tn - j * 3) * KT;
            const int dlt  = c_dlt[cls][j];
            const int wofs = c_wofs[cls][j];
#pragma unroll
            for (int l = 0; l < 8; l++) {
                int flat = tid + l * 256;
                int kr = flat >> 6, col = flat & 63;
                rA[l] = __ldg(&xpb[(c96b + kr) * 1024 + mbase + col + dlt]);
            }
#pragma unroll
            for (int l = 0; l < 2; l++) {
                int f4 = tid + l * 256;
                int kr = f4 >> 4, n4 = f4 & 15;
                rB[l] = *(const float4*)&g_Wc[(size_t)(c96b + kr) * 576 + wofs + n4 * 4];
            }
        }

#pragma unroll
        for (int kk = 0; kk < KT; kk++) {
            float4 a  = *(const float4*)&sA[buf][kk * MT + m0];
            float4 bb = *(const float4*)&sB[buf][kk * 64 + n0];
            acc[0]  = fmaf(a.x, bb.x, acc[0]);
            acc[1]  = fmaf(a.x, bb.y, acc[1]);
            acc[2]  = fmaf(a.x, bb.z, acc[2]);
            acc[3]  = fmaf(a.x, bb.w, acc[3]);
            acc[4]  = fmaf(a.y, bb.x, acc[4]);
            acc[5]  = fmaf(a.y, bb.y, acc[5]);
            acc[6]  = fmaf(a.y, bb.z, acc[6]);
            acc[7]  = fmaf(a.y, bb.w, acc[7]);
            acc[8]  = fmaf(a.z, bb.x, acc[8]);
            acc[9]  = fmaf(a.z, bb.y, acc[9]);
            acc[10] = fmaf(a.z, bb.z, acc[10]);
            acc[11] = fmaf(a.z, bb.w, acc[11]);
            acc[12] = fmaf(a.w, bb.x, acc[12]);
            acc[13] = fmaf(a.w, bb.y, acc[13]);
            acc[14] = fmaf(a.w, bb.z, acc[14]);
            acc[15] = fmaf(a.w, bb.w, acc[15]);
        }
        // no second barrier: next iteration writes buf^1, which no warp reads now
        if (t + 1 < ntiles) __syncthreads();   // protect buf^1 store vs slow readers of buf
    }

    // ---- fused epilogue: mean-scale + biases + channel softmax + 2*tanh ----
    const float inv_d = 1.0f / 31.0f;
    float cbs[4];
#pragma unroll
    for (int j = 0; j < 4; j++) cbs[j] = s_cb[n0 + j];
    const int oh = c_oh[cls], ow = c_ow[cls];

#pragma unroll
    for (int mi = 0; mi < 4; mi++) {
        float t0 = acc[mi * 4 + 0] * inv_d + cbs[0];
        float t1 = acc[mi * 4 + 1] * inv_d + cbs[1];
        float t2 = acc[mi * 4 + 2] * inv_d + cbs[2];
        float t3 = acc[mi * 4 + 3] * inv_d + cbs[3];
        float mx = fmaxf(fmaxf(t0, t1), fmaxf(t2, t3));
#pragma unroll
        for (int o = 1; o <= 8; o <<= 1)
            mx = fmaxf(mx, __shfl_xor_sync(0xffffffffu, mx, o));
        float e0 = __expf(t0 - mx), e1 = __expf(t1 - mx);
        float e2 = __expf(t2 - mx), e3 = __expf(t3 - mx);
        float sum = (e0 + e1) + (e2 + e3);
#pragma unroll
        for (int o = 1; o <= 8; o <<= 1)
            sum += __shfl_xor_sync(0xffffffffu, sum, o);
        float rs = 1.0f / sum;

        int m = mbase + m0 + mi;
        int hq = m >> 5, wq = m & 31;
        int ho = 2 * hq + oh, wo = 2 * wq + ow;
        if (ho < HOUT && wo < HOUT) {
            size_t pix = (size_t)ho * HOUT + wo;
            float e[4] = {e0, e1, e2, e3};
#pragma unroll
            for (int j = 0; j < 4; j++) {
                float s = e[j] * rs;
                float tt = __expf(-2.0f * s);
                float r = __fdividef(4.0f, 1.0f + tt) - 2.0f;   // 2*tanh(s)
                out[((size_t)(b * COUT + n0 + j)) * (HOUT * HOUT) + pix] = r;
            }
        }
    }
}

extern "C" void kernel_launch(void* const* d_in, const int* in_sizes, int n_in,
                              void* d_out, int out_size) {
    (void)in_sizes; (void)n_in; (void)out_size;
    const float* x         = (const float*)d_in[0];
    const float* w         = (const float*)d_in[1];
    const float* conv_bias = (const float*)d_in[2];
    const float* bias      = (const float*)d_in[3];
    float* out             = (float*)d_out;

    prep_x_kernel<<<(NB * CIN * 256) / 128, 128>>>(x);
    wc_kernel<<<(96 * 576 + 255) / 256, 256>>>(w);
    gemm_fused<<<512, 256>>>(conv_bias, bias, out);
}

// round 7
// speedup vs baseline: 1.7372x; 1.0543x over previous
#include <cuda_runtime.h>
#include <cuda_bf16.h>
#include <math.h>
#include <cstdint>

#define NB 8
#define COUT 64
#define HOUT 63

// ---- scratch (device globals, zero-initialized; no cudaMalloc) ----
// XA: [b][m 1072 (pad>=1024+33)][kpair 48] -> uint2 = (h0|h1<<16, l0|l1<<16)
__device__ __align__(16) uint2 g_XA[NB * 1072 * 48];
// WB: [plane 9][n 64][kpair 48] -> uint2
__device__ __align__(16) uint2 g_WB[9 * 64 * 48];

// classes (heavy first): 0=oo(4 planes) 1=oe(2) 2=eo(2) 3=ee(1)
__constant__ int c_dlt[4][4]  = {{33,32,1,0},{32,0,0,0},{1,0,0,0},{0,0,0,0}};
__constant__ int c_wrow[4][4] = {{0,128,384,512},{64,448,0,0},{192,320,0,0},{256,0,0,0}}; // (kh*3+kw)*64
__constant__ int c_np[4] = {4, 2, 2, 1};
__constant__ int c_oh[4] = {1, 1, 0, 0};
__constant__ int c_ow[4] = {1, 0, 1, 0};

// ================= fused prep+pack: x -> bf16 hi/lo, m-major, kpair-interleaved =================
// block = (b, mb of 64 m). Read all 16 depth planes once; planes: 0=sum_d, 1=d0, 2=d15.
__global__ void __launch_bounds__(256)
prep_pack_kernel(const float* __restrict__ x) {
    __shared__ float sm[3][32][65];
    const int b  = blockIdx.x >> 4;
    const int mb = blockIdx.x & 15;
    const int tid = threadIdx.x;
    const int ci = tid >> 3;
    const int mg = tid & 7;

    const float4* p = (const float4*)x + ((size_t)(b * 32 + ci) * 16) * 256 + mb * 16 + mg * 2;
    float4 va = p[0], vb = p[1];
    float4 sa = va, sb = vb;
    float4 d0a = va, d0b = vb;
    float4 d15a = va, d15b = vb;
#pragma unroll
    for (int d = 1; d < 16; d++) {
        float4 u = p[d * 256], v2 = p[d * 256 + 1];
        sa.x += u.x;  sa.y += u.y;  sa.z += u.z;  sa.w += u.w;
        sb.x += v2.x; sb.y += v2.y; sb.z += v2.z; sb.w += v2.w;
        if (d == 15) { d15a = u; d15b = v2; }
    }
    const int mo = mg * 8;
    sm[0][ci][mo + 0] = sa.x;  sm[0][ci][mo + 1] = sa.y;
    sm[0][ci][mo + 2] = sa.z;  sm[0][ci][mo + 3] = sa.w;
    sm[0][ci][mo + 4] = sb.x;  sm[0][ci][mo + 5] = sb.y;
    sm[0][ci][mo + 6] = sb.z;  sm[0][ci][mo + 7] = sb.w;
    sm[1][ci][mo + 0] = d0a.x; sm[1][ci][mo + 1] = d0a.y;
    sm[1][ci][mo + 2] = d0a.z; sm[1][ci][mo + 3] = d0a.w;
    sm[1][ci][mo + 4] = d0b.x; sm[1][ci][mo + 5] = d0b.y;
    sm[1][ci][mo + 6] = d0b.z; sm[1][ci][mo + 7] = d0b.w;
    sm[2][ci][mo + 0] = d15a.x; sm[2][ci][mo + 1] = d15a.y;
    sm[2][ci][mo + 2] = d15a.z; sm[2][ci][mo + 3] = d15a.w;
    sm[2][ci][mo + 4] = d15b.x; sm[2][ci][mo + 5] = d15b.y;
    sm[2][ci][mo + 6] = d15b.z; sm[2][ci][mo + 7] = d15b.w;
    __syncthreads();

#pragma unroll
    for (int it = 0; it < 12; it++) {
        int i = tid + it * 256;              // 0 .. 64*48-1
        int row = i / 48;
        int kp  = i - row * 48;
        int s  = kp >> 4;                    // 16 kpairs (32 k) per plane
        int c0 = (2 * kp) & 31;
        float f0 = sm[s][c0][row];
        float f1 = sm[s][c0 + 1][row];
        __nv_bfloat16 h0 = __float2bfloat16(f0);
        __nv_bfloat16 h1 = __float2bfloat16(f1);
        __nv_bfloat16 l0 = __float2bfloat16(f0 - __bfloat162float(h0));
        __nv_bfloat16 l1 = __float2bfloat16(f1 - __bfloat162float(h1));
        uint32_t h = (uint32_t)__bfloat16_as_ushort(h0) | ((uint32_t)__bfloat16_as_ushort(h1) << 16);
        uint32_t l = (uint32_t)__bfloat16_as_ushort(l0) | ((uint32_t)__bfloat16_as_ushort(l1) << 16);
        g_XA[((size_t)b * 1072 + mb * 64 + row) * 48 + kp] = make_uint2(h, l);
    }
}

// ================= wc: combine weights over kd -> bf16 hi/lo, kpair-interleaved =================
// w layout: (ci, co, kd, kh, kw). c96 = s*32+ci; s0: sum_kd; s1: -w[kd=0]; s2: -w[kd=2]
__global__ void __launch_bounds__(256)
wc_kernel(const float* __restrict__ w) {
    int i = blockIdx.x * 256 + threadIdx.x;   // 0 .. 9*64*48-1
    if (i >= 9 * 64 * 48) return;
    int kp  = i % 48;
    int n   = (i / 48) & 63;
    int pid = i / (48 * 64);
    int kh = pid / 3, kw = pid % 3;
    float f[2];
#pragma unroll
    for (int j = 0; j < 2; j++) {
        int c96 = 2 * kp + j;
        int s = c96 >> 5, ci = c96 & 31;
        int base = (ci * 64 + n) * 27 + kh * 3 + kw;
        float v;
        if (s == 0)      v = w[base] + w[base + 9] + w[base + 18];
        else if (s == 1) v = -w[base];
        else             v = -w[base + 18];
        f[j] = v;
    }
    __nv_bfloat16 h0 = __float2bfloat16(f[0]);
    __nv_bfloat16 h1 = __float2bfloat16(f[1]);
    __nv_bfloat16 l0 = __float2bfloat16(f[0] - __bfloat162float(h0));
    __nv_bfloat16 l1 = __float2bfloat16(f[1] - __bfloat162float(h1));
    uint32_t h = (uint32_t)__bfloat16_as_ushort(h0) | ((uint32_t)__bfloat16_as_ushort(h1) << 16);
    uint32_t l = (uint32_t)__bfloat16_as_ushort(l0) | ((uint32_t)__bfloat16_as_ushort(l1) << 16);
    g_WB[i] = make_uint2(h, l);
}

// ================= HMMA GEMM + fused mean/bias/softmax/tanh =================
__device__ __forceinline__ void mma16816(float* d,
                                         uint32_t a0, uint32_t a1, uint32_t a2, uint32_t a3,
                                         uint32_t b0, uint32_t b1) {
    asm volatile(
        "mma.sync.aligned.m16n8k16.row.col.f32.bf16.bf16.f32 "
        "{%0,%1,%2,%3},{%4,%5,%6,%7},{%8,%9},{%0,%1,%2,%3};"
        : "+f"(d[0]), "+f"(d[1]), "+f"(d[2]), "+f"(d[3])
        : "r"(a0), "r"(a1), "r"(a2), "r"(a3), "r"(b0), "r"(b1));
}

// grid 256: cls=bid>>6 (heavy first), b=(bid>>3)&7, mt=bid&7. Block 128m x 64n.
// 8 warps; warp w owns m rows [mbase+16w, +16). 3-split bf16 MMA, fp32 accum.
__global__ void __launch_bounds__(256)
mma_fused(const float* __restrict__ conv_bias,
          const float* __restrict__ bias,
          float* __restrict__ out) {
    __shared__ float scb[COUT];
    const int tid  = threadIdx.x;
    const int w    = tid >> 5;
    const int lane = tid & 31;
    if (tid < COUT) scb[tid] = conv_bias[tid] + bias[tid];
    __syncthreads();

    const int bid = blockIdx.x;
    const int cls = bid >> 6;
    const int b   = (bid >> 3) & 7;
    const int mt  = bid & 7;
    const int mbase = mt * 128;
    const int mw = mbase + w * 16;
    const int qr = lane >> 2;     // 0..7
    const int qc = lane & 3;      // 0..3

    float acc[8][4];
#pragma unroll
    for (int j = 0; j < 8; j++)
#pragma unroll
        for (int t = 0; t < 4; t++) acc[j][t] = 0.f;

    const int NP = c_np[cls];
    for (int pl = 0; pl < NP; pl++) {
        const int dlt  = c_dlt[cls][pl];
        const uint2* __restrict__ Ab = g_XA + ((size_t)b * 1072 + mw + dlt + qr) * 48 + qc;
        const uint2* __restrict__ Bb = g_WB + ((size_t)c_wrow[cls][pl] + qr) * 48 + qc;
#pragma unroll
        for (int ks = 0; ks < 6; ks++) {
            const int ko = ks * 8;
            uint2 a0 = Ab[ko];
            uint2 a2 = Ab[ko + 4];
            uint2 a1 = Ab[ko + 8 * 48];
            uint2 a3 = Ab[ko + 4 + 8 * 48];
#pragma unroll
            for (int jn = 0; jn < 8; jn++) {
                uint2 b0 = Bb[jn * 8 * 48 + ko];
                uint2 b1 = Bb[jn * 8 * 48 + ko + 4];
                mma16816(acc[jn], a0.x, a1.x, a2.x, a3.x, b0.x, b1.x);  // ah*bh
                mma16816(acc[jn], a0.y, a1.y, a2.y, a3.y, b0.x, b1.x);  // al*bh
                mma16816(acc[jn], a0.x, a1.x, a2.x, a3.x, b0.y, b1.y);  // ah*bl
            }
        }
    }

    // ---- fused epilogue ----
    // D frag: d0,d1 -> row qr,  cols jn*8 + 2*qc + {0,1}
    //         d2,d3 -> row qr+8, same cols.
    // Lane quad (xor 1,2) covers all 64 channels of both pixels.
    const float inv_d = 1.0f / 31.0f;
    float mx0 = -INFINITY, mx1 = -INFINITY;
#pragma unroll
    for (int jn = 0; jn < 8; jn++) {
#pragma unroll
        for (int t = 0; t < 2; t++) {
            float c = scb[jn * 8 + 2 * qc + t];
            acc[jn][t]     = acc[jn][t]     * inv_d + c;
            acc[jn][2 + t] = acc[jn][2 + t] * inv_d + c;
            mx0 = fmaxf(mx0, acc[jn][t]);
            mx1 = fmaxf(mx1, acc[jn][2 + t]);
        }
    }
    mx0 = fmaxf(mx0, __shfl_xor_sync(0xffffffffu, mx0, 1));
    mx0 = fmaxf(mx0, __shfl_xor_sync(0xffffffffu, mx0, 2));
    mx1 = fmaxf(mx1, __shfl_xor_sync(0xffffffffu, mx1, 1));
    mx1 = fmaxf(mx1, __shfl_xor_sync(0xffffffffu, mx1, 2));

    float s0 = 0.f, s1 = 0.f;
#pragma unroll
    for (int jn = 0; jn < 8; jn++) {
#pragma unroll
        for (int t = 0; t < 2; t++) {
            acc[jn][t]     = __expf(acc[jn][t] - mx0);
            acc[jn][2 + t] = __expf(acc[jn][2 + t] - mx1);
            s0 += acc[jn][t];
            s1 += acc[jn][2 + t];
        }
    }
    s0 += __shfl_xor_sync(0xffffffffu, s0, 1);
    s0 += __shfl_xor_sync(0xffffffffu, s0, 2);
    s1 += __shfl_xor_sync(0xffffffffu, s1, 1);
    s1 += __shfl_xor_sync(0xffffffffu, s1, 2);
    const float rs0 = 1.0f / s0;
    const float rs1 = 1.0f / s1;

    const int oh = c_oh[cls], ow = c_ow[cls];
    const int m0 = mw + qr;              // pixel 0 (rows d0,d1)
    const int hq = m0 >> 5;
    const int wq0 = m0 & 31;
    const int ho = 2 * hq + oh;
    const int wo0 = 2 * wq0 + ow;
    const int wo1 = 2 * (wq0 + 8) + ow;  // pixel 1 (rows d2,d3), same ho
    float* obase = out + (size_t)b * COUT * (HOUT * HOUT) + (size_t)ho * HOUT;

    if (ho < HOUT) {
        const bool v0 = (wo0 < HOUT);
        const bool v1 = (wo1 < HOUT);
#pragma unroll
        for (int jn = 0; jn < 8; jn++) {
#pragma unroll
            for (int t = 0; t < 2; t++) {
                int ch = jn * 8 + 2 * qc + t;
                float* op = obase + (size_t)ch * (HOUT * HOUT);
                if (v0) {
                    float s = acc[jn][t] * rs0;
                    op[wo0] = __fdividef(4.0f, 1.0f + __expf(-2.0f * s)) - 2.0f;  // 2*tanh
                }
                if (v1) {
                    float s = acc[jn][2 + t] * rs1;
                    op[wo1] = __fdividef(4.0f, 1.0f + __expf(-2.0f * s)) - 2.0f;
                }
            }
        }
    }
}

extern "C" void kernel_launch(void* const* d_in, const int* in_sizes, int n_in,
                              void* d_out, int out_size) {
    (void)in_sizes; (void)n_in; (void)out_size;
    const float* x         = (const float*)d_in[0];
    const float* w         = (const float*)d_in[1];
    const float* conv_bias = (const float*)d_in[2];
    const float* bias      = (const float*)d_in[3];
    float* out             = (float*)d_out;

    prep_pack_kernel<<<NB * 16, 256>>>(x);
    wc_kernel<<<(9 * 64 * 48 + 255) / 256, 256>>>(w);
    mma_fused<<<256, 256>>>(conv_bias, bias, out);
}

// round 8
// speedup vs baseline: 2.4572x; 1.4145x over previous
#include <cuda_runtime.h>
#include <cuda_fp16.h>
#include <math.h>
#include <cstdint>

#define NB 8
#define COUT 64
#define HOUT 63

// ---- scratch (device globals, zero-initialized; no cudaMalloc) ----
// XA: [b][m 1072 (pad>=1024+33)][kpair 48] -> uint2 = (ah0|ah1<<16, al0|al1<<16) fp16
__device__ __align__(16) uint2 g_XA[NB * 1072 * 48];
// WB: [plane 9][n 64][kpair 48] -> uint32 = (bh0|bh1<<16) fp16 (hi only)
__device__ __align__(16) uint32_t g_WB[9 * 64 * 48];

// classes (heavy first): 0=oo(4 planes) 1=oe(2) 2=eo(2) 3=ee(1)
__constant__ int c_dlt[4][4]  = {{33,32,1,0},{32,0,0,0},{1,0,0,0},{0,0,0,0}};
__constant__ int c_wrow[4][4] = {{0,128,384,512},{64,448,0,0},{192,320,0,0},{256,0,0,0}}; // (kh*3+kw)*64
__constant__ int c_np[4] = {4, 2, 2, 1};
__constant__ int c_oh[4] = {1, 1, 0, 0};
__constant__ int c_ow[4] = {1, 0, 1, 0};

__device__ __forceinline__ uint32_t pack_h2(float f0, float f1) {
    __half h0 = __float2half_rn(f0);
    __half h1 = __float2half_rn(f1);
    return (uint32_t)__half_as_ushort(h0) | ((uint32_t)__half_as_ushort(h1) << 16);
}

// ================= fused prep+pack (+wc): single launch =================
// blocks [0,512): prep — b=bx>>6, 16 m-cols each. blocks [512,728): wc.
__global__ void __launch_bounds__(128)
prep_kernel(const float* __restrict__ x, const float* __restrict__ w) {
    if (blockIdx.x < 512) {
        __shared__ float sm[3][32][17];
        const int b    = blockIdx.x >> 6;
        const int mb16 = blockIdx.x & 63;        // 16-m tile
        const int tid  = threadIdx.x;
        const int ci = tid >> 2;                  // 0..31
        const int mg = tid & 3;                   // 4 float4 = 16 m

        const float4* p = (const float4*)x + ((size_t)(b * 32 + ci) * 16) * 256 + mb16 * 4 + mg;
        float4 v = p[0];
        float4 s = v, d0 = v, d15 = v;
#pragma unroll
        for (int d = 1; d < 16; d++) {
            float4 u = p[d * 256];
            s.x += u.x; s.y += u.y; s.z += u.z; s.w += u.w;
            if (d == 15) d15 = u;
        }
        const int mo = mg * 4;
        sm[0][ci][mo + 0] = s.x;   sm[0][ci][mo + 1] = s.y;
        sm[0][ci][mo + 2] = s.z;   sm[0][ci][mo + 3] = s.w;
        sm[1][ci][mo + 0] = d0.x;  sm[1][ci][mo + 1] = d0.y;
        sm[1][ci][mo + 2] = d0.z;  sm[1][ci][mo + 3] = d0.w;
        sm[2][ci][mo + 0] = d15.x; sm[2][ci][mo + 1] = d15.y;
        sm[2][ci][mo + 2] = d15.z; sm[2][ci][mo + 3] = d15.w;
        __syncthreads();

#pragma unroll
        for (int it = 0; it < 6; it++) {
            int i = tid + it * 128;              // 0 .. 16*48-1
            int row = i / 48;                    // m within tile
            int kp  = i - row * 48;
            int sp  = kp >> 4;                   // plane: 0=sum,1=d0,2=d15
            int c0  = (2 * kp) & 31;
            float f0 = sm[sp][c0][row];
            float f1 = sm[sp][c0 + 1][row];
            __half h0 = __float2half_rn(f0);
            __half h1 = __float2half_rn(f1);
            float l0 = f0 - __half2float(h0);
            float l1 = f1 - __half2float(h1);
            uint32_t hh = (uint32_t)__half_as_ushort(h0) | ((uint32_t)__half_as_ushort(h1) << 16);
            uint32_t ll = pack_h2(l0, l1);
            g_XA[((size_t)b * 1072 + mb16 * 16 + row) * 48 + kp] = make_uint2(hh, ll);
        }
    } else {
        // wc: combine weights over kd -> fp16 (hi only), kpair-packed
        int i = (blockIdx.x - 512) * 128 + threadIdx.x;   // 0 .. 9*64*48-1
        if (i >= 9 * 64 * 48) return;
        int kp  = i % 48;
        int n   = (i / 48) & 63;
        int pid = i / (48 * 64);
        int kh = pid / 3, kw = pid % 3;
        float f[2];
#pragma unroll
        for (int j = 0; j < 2; j++) {
            int c96 = 2 * kp + j;
            int sidx = c96 >> 5, ci = c96 & 31;
            int base = (ci * 64 + n) * 27 + kh * 3 + kw;
            float v;
            if (sidx == 0)      v = w[base] + w[base + 9] + w[base + 18];
            else if (sidx == 1) v = -w[base];
            else                v = -w[base + 18];
            f[j] = v;
        }
        g_WB[i] = pack_h2(f[0], f[1]);
    }
}

// ================= HMMA GEMM + fused mean/bias/softmax/tanh =================
__device__ __forceinline__ void mma16816(float* d,
                                         uint32_t a0, uint32_t a1, uint32_t a2, uint32_t a3,
                                         uint32_t b0, uint32_t b1) {
    asm volatile(
        "mma.sync.aligned.m16n8k16.row.col.f32.f16.f16.f32 "
        "{%0,%1,%2,%3},{%4,%5,%6,%7},{%8,%9},{%0,%1,%2,%3};"
        : "+f"(d[0]), "+f"(d[1]), "+f"(d[2]), "+f"(d[3])
        : "r"(a0), "r"(a1), "r"(a2), "r"(a3), "r"(b0), "r"(b1));
}

// grid 256: cls=bid>>6 (heavy first), b=(bid>>3)&7, mt=bid&7. Block 128m x 64n.
// 8 warps; warp w owns m rows [mbase+16w, +16). fp16 2-split (ah+al)*bh, fp32 accum.
__global__ void __launch_bounds__(256)
mma_fused(const float* __restrict__ conv_bias,
          const float* __restrict__ bias,
          float* __restrict__ out) {
    __shared__ float scb[COUT];
    const int tid  = threadIdx.x;
    const int w    = tid >> 5;
    const int lane = tid & 31;
    if (tid < COUT) scb[tid] = conv_bias[tid] + bias[tid];
    __syncthreads();

    const int bid = blockIdx.x;
    const int cls = bid >> 6;
    const int b   = (bid >> 3) & 7;
    const int mt  = bid & 7;
    const int mbase = mt * 128;
    const int mw = mbase + w * 16;
    const int qr = lane >> 2;     // 0..7
    const int qc = lane & 3;      // 0..3

    float acc[8][4];
#pragma unroll
    for (int j = 0; j < 8; j++)
#pragma unroll
        for (int t = 0; t < 4; t++) acc[j][t] = 0.f;

    const int NP = c_np[cls];
    for (int pl = 0; pl < NP; pl++) {
        const int dlt  = c_dlt[cls][pl];
        const uint2*    __restrict__ Ab = g_XA + ((size_t)b * 1072 + mw + dlt + qr) * 48 + qc;
        const uint32_t* __restrict__ Bb = g_WB + ((size_t)c_wrow[cls][pl] + qr) * 48 + qc;
#pragma unroll
        for (int ks = 0; ks < 6; ks++) {
            const int ko = ks * 8;
            uint2 a0 = Ab[ko];
            uint2 a2 = Ab[ko + 4];
            uint2 a1 = Ab[ko + 8 * 48];
            uint2 a3 = Ab[ko + 4 + 8 * 48];
#pragma unroll
            for (int jn = 0; jn < 8; jn++) {
                uint32_t b0 = Bb[jn * 8 * 48 + ko];
                uint32_t b1 = Bb[jn * 8 * 48 + ko + 4];
                mma16816(acc[jn], a0.x, a1.x, a2.x, a3.x, b0, b1);  // ah*bh
                mma16816(acc[jn], a0.y, a1.y, a2.y, a3.y, b0, b1);  // al*bh
            }
        }
    }

    // ---- fused epilogue ----
    // D frag: d0,d1 -> row qr (pixel0), cols jn*8 + 2*qc + {0,1}; d2,d3 -> row qr+8 (pixel1).
    const float inv_d = 1.0f / 31.0f;
    float mx0 = -INFINITY, mx1 = -INFINITY;
#pragma unroll
    for (int jn = 0; jn < 8; jn++) {
#pragma unroll
        for (int t = 0; t < 2; t++) {
            float c = scb[jn * 8 + 2 * qc + t];
            acc[jn][t]     = acc[jn][t]     * inv_d + c;
            acc[jn][2 + t] = acc[jn][2 + t] * inv_d + c;
            mx0 = fmaxf(mx0, acc[jn][t]);
            mx1 = fmaxf(mx1, acc[jn][2 + t]);
        }
    }
    mx0 = fmaxf(mx0, __shfl_xor_sync(0xffffffffu, mx0, 1));
    mx0 = fmaxf(mx0, __shfl_xor_sync(0xffffffffu, mx0, 2));
    mx1 = fmaxf(mx1, __shfl_xor_sync(0xffffffffu, mx1, 1));
    mx1 = fmaxf(mx1, __shfl_xor_sync(0xffffffffu, mx1, 2));

    float s0 = 0.f, s1 = 0.f;
#pragma unroll
    for (int jn = 0; jn < 8; jn++) {
#pragma unroll
        for (int t = 0; t < 2; t++) {
            acc[jn][t]     = __expf(acc[jn][t] - mx0);
            acc[jn][2 + t] = __expf(acc[jn][2 + t] - mx1);
            s0 += acc[jn][t];
            s1 += acc[jn][2 + t];
        }
    }
    s0 += __shfl_xor_sync(0xffffffffu, s0, 1);
    s0 += __shfl_xor_sync(0xffffffffu, s0, 2);
    s1 += __shfl_xor_sync(0xffffffffu, s1, 1);
    s1 += __shfl_xor_sync(0xffffffffu, s1, 2);
    const float rs0 = 1.0f / s0;
    const float rs1 = 1.0f / s1;

    const int oh = c_oh[cls], ow = c_ow[cls];
    const int m0 = mw + qr;
    const int hq = m0 >> 5;
    const int wq0 = m0 & 31;
    const int ho = 2 * hq + oh;
    const int wo0 = 2 * wq0 + ow;
    const int wo1 = 2 * (wq0 + 8) + ow;
    float* obase = out + (size_t)b * COUT * (HOUT * HOUT) + (size_t)ho * HOUT;

    if (ho < HOUT) {
        const bool v0 = (wo0 < HOUT);
        const bool v1 = (wo1 < HOUT);
#pragma unroll
        for (int jn = 0; jn < 8; jn++) {
#pragma unroll
            for (int t = 0; t < 2; t++) {
                int ch = jn * 8 + 2 * qc + t;
                float* op = obase + (size_t)ch * (HOUT * HOUT);
                if (v0) {
                    float s = acc[jn][t] * rs0;
                    op[wo0] = __fdividef(4.0f, 1.0f + __expf(-2.0f * s)) - 2.0f;  // 2*tanh
                }
                if (v1) {
                    float s = acc[jn][2 + t] * rs1;
                    op[wo1] = __fdividef(4.0f, 1.0f + __expf(-2.0f * s)) - 2.0f;
                }
            }
        }
    }
}

extern "C" void kernel_launch(void* const* d_in, const int* in_sizes, int n_in,
                              void* d_out, int out_size) {
    (void)in_sizes; (void)n_in; (void)out_size;
    const float* x         = (const float*)d_in[0];
    const float* w         = (const float*)d_in[1];
    const float* conv_bias = (const float*)d_in[2];
    const float* bias      = (const float*)d_in[3];
    float* out             = (float*)d_out;

    // 512 prep blocks + ceil(9*64*48 / 128)=216 wc blocks
    prep_kernel<<<728, 128>>>(x, w);
    mma_fused<<<256, 256>>>(conv_bias, bias, out);
}

// round 9
// speedup vs baseline: 2.9104x; 1.1844x over previous
#include <cuda_runtime.h>
#include <cuda_fp16.h>
#include <math.h>
#include <cstdint>

#define NB 8
#define COUT 64
#define HOUT 63

// ---- scratch (device globals, zero-initialized; no cudaMalloc) ----
// XA2: [b][ks 6][m 1072][qc 4] -> uint4 = (hA, hB, lA, lB); kpA=ks*8+qc, kpB=kpA+4
__device__ __align__(16) uint4 g_XA2[NB * 6 * 1072 * 4];
// WB2: [pl 9][jn 8][ks 6][lane 32] -> uint2 = (b0, b1) fragment regs (hi only)
__device__ __align__(16) uint2 g_WB2[9 * 8 * 6 * 32];

// classes (heavy first): 0=oo(4 planes) 1=oe(2) 2=eo(2) 3=ee(1)
__constant__ int c_dlt[4][4] = {{33,32,1,0},{32,0,0,0},{1,0,0,0},{0,0,0,0}};
__constant__ int c_pl[4][4]  = {{0,2,6,8},{1,7,0,0},{3,5,0,0},{4,0,0,0}};  // plane id kh*3+kw
__constant__ int c_np[4] = {4, 2, 2, 1};
__constant__ int c_oh[4] = {1, 1, 0, 0};
__constant__ int c_ow[4] = {1, 0, 1, 0};

__device__ __forceinline__ uint32_t pack_h2(float f0, float f1) {
    __half h0 = __float2half_rn(f0);
    __half h1 = __float2half_rn(f1);
    return (uint32_t)__half_as_ushort(h0) | ((uint32_t)__half_as_ushort(h1) << 16);
}

// ================= prep (+wc) single launch =================
// blocks [0,512): prep x. blocks [512, 512+108): wc weights.
__global__ void __launch_bounds__(128)
prep_kernel(const float* __restrict__ x, const float* __restrict__ w) {
    if (blockIdx.x < 512) {
        __shared__ float sm[3][32][17];
        const int b    = blockIdx.x >> 6;
        const int mb16 = blockIdx.x & 63;       // 16-m tile
        const int tid  = threadIdx.x;
        const int ci = tid >> 2;
        const int mg = tid & 3;

        const float4* p = (const float4*)x + ((size_t)(b * 32 + ci) * 16) * 256 + mb16 * 4 + mg;
        float4 v = p[0];
        float4 s = v, d0 = v, d15 = v;
#pragma unroll
        for (int d = 1; d < 16; d++) {
            float4 u = p[d * 256];
            s.x += u.x; s.y += u.y; s.z += u.z; s.w += u.w;
            if (d == 15) d15 = u;
        }
        const int mo = mg * 4;
        sm[0][ci][mo + 0] = s.x;   sm[0][ci][mo + 1] = s.y;
        sm[0][ci][mo + 2] = s.z;   sm[0][ci][mo + 3] = s.w;
        sm[1][ci][mo + 0] = d0.x;  sm[1][ci][mo + 1] = d0.y;
        sm[1][ci][mo + 2] = d0.z;  sm[1][ci][mo + 3] = d0.w;
        sm[2][ci][mo + 0] = d15.x; sm[2][ci][mo + 1] = d15.y;
        sm[2][ci][mo + 2] = d15.z; sm[2][ci][mo + 3] = d15.w;
        __syncthreads();

#pragma unroll
        for (int it = 0; it < 3; it++) {
            int i = tid + it * 128;             // 0 .. 16*6*4-1
            int qc  = i & 3;
            int ks  = (i >> 2) % 6;
            int row = i / 24;
            int kpA = ks * 8 + qc;
            int kpB = kpA + 4;
            int spA = kpA >> 4, cA = (2 * kpA) & 31;
            int spB = kpB >> 4, cB = (2 * kpB) & 31;
            float fA0 = sm[spA][cA][row],     fA1 = sm[spA][cA + 1][row];
            float fB0 = sm[spB][cB][row],     fB1 = sm[spB][cB + 1][row];
            __half hA0 = __float2half_rn(fA0), hA1 = __float2half_rn(fA1);
            __half hB0 = __float2half_rn(fB0), hB1 = __float2half_rn(fB1);
            uint32_t hA = (uint32_t)__half_as_ushort(hA0) | ((uint32_t)__half_as_ushort(hA1) << 16);
            uint32_t hB = (uint32_t)__half_as_ushort(hB0) | ((uint32_t)__half_as_ushort(hB1) << 16);
            uint32_t lA = pack_h2(fA0 - __half2float(hA0), fA1 - __half2float(hA1));
            uint32_t lB = pack_h2(fB0 - __half2float(hB0), fB1 - __half2float(hB1));
            size_t idx = (((size_t)b * 6 + ks) * 1072 + mb16 * 16 + row) * 4 + qc;
            g_XA2[idx] = make_uint4(hA, hB, lA, lB);
        }
    } else {
        // wc -> fragment layout [pl][jn][ks][lane]
        int i = (blockIdx.x - 512) * 128 + threadIdx.x;   // 0 .. 9*8*6*32-1
        if (i >= 9 * 8 * 6 * 32) return;
        int lane = i & 31;
        int ks   = (i >> 5) % 6;
        int jn   = (i / 192) & 7;
        int pl   = i / 1536;
        int qr = lane >> 2, qc = lane & 3;
        int n  = jn * 8 + qr;
        int kh = pl / 3, kw = pl % 3;
        float f[4];
#pragma unroll
        for (int j = 0; j < 4; j++) {
            int kp  = ks * 8 + qc + (j >> 1) * 4;      // kpA, kpA, kpB, kpB
            int c96 = 2 * kp + (j & 1);
            int sidx = c96 >> 5, ci = c96 & 31;
            int base = (ci * 64 + n) * 27 + kh * 3 + kw;
            float v;
            if (sidx == 0)      v = w[base] + w[base + 9] + w[base + 18];
            else if (sidx == 1) v = -w[base];
            else                v = -w[base + 18];
            f[j] = v;
        }
        g_WB2[i] = make_uint2(pack_h2(f[0], f[1]), pack_h2(f[2], f[3]));
    }
}

// ================= HMMA GEMM (2-way k-split) + fused epilogue =================
__device__ __forceinline__ void mma16816(float* d,
                                         uint32_t a0, uint32_t a1, uint32_t a2, uint32_t a3,
                                         uint32_t b0, uint32_t b1) {
    asm volatile(
        "mma.sync.aligned.m16n8k16.row.col.f32.f16.f16.f32 "
        "{%0,%1,%2,%3},{%4,%5,%6,%7},{%8,%9},{%0,%1,%2,%3};"
        : "+f"(d[0]), "+f"(d[1]), "+f"(d[2]), "+f"(d[3])
        : "r"(a0), "r"(a1), "r"(a2), "r"(a3), "r"(b0), "r"(b1));
}

// grid 512: cls=bid>>7 (heavy first), b=(bid>>4)&7, mt=bid&15. Block 64m x 64n.
// 8 warps: grp=w>>2 splits ksteps; warp handles m rows [mt*64 + (w&3)*16, +16).
__global__ void __launch_bounds__(256, 3)
mma_fused(const float* __restrict__ conv_bias,
          const float* __restrict__ bias,
          float* __restrict__ out) {
    __shared__ float scb[COUT];
    __shared__ float red[4][32][32];     // 16KB reduction buffer

    const int tid  = threadIdx.x;
    const int w    = tid >> 5;
    const int lane = tid & 31;
    const int wm   = w & 3;
    const int grp  = w >> 2;
    if (tid < COUT) scb[tid] = conv_bias[tid] + bias[tid];

    const int bid = blockIdx.x;
    const int cls = bid >> 7;
    const int b   = (bid >> 4) & 7;
    const int mt  = bid & 15;
    const int mw  = mt * 64 + wm * 16;
    const int qr = lane >> 2;
    const int qc = lane & 3;

    float acc[8][4];
#pragma unroll
    for (int j = 0; j < 8; j++)
#pragma unroll
        for (int t = 0; t < 4; t++) acc[j][t] = 0.f;

    const int halfT = c_np[cls] * 3;
    const int sb = grp * halfT;
    for (int s = sb; s < sb + halfT; s++) {
        const int pli = s / 6;                    // class-local plane index
        const int ks  = s - pli * 6;
        const int dlt = c_dlt[cls][pli];
        const int pl  = c_pl[cls][pli];

        const uint4* __restrict__ A0 =
            g_XA2 + (((size_t)b * 6 + ks) * 1072 + mw + dlt + qr) * 4 + qc;
        const uint2* __restrict__ B0 =
            g_WB2 + ((size_t)pl * 8 * 6 + ks) * 32 + lane;

        uint4 av0 = A0[0];        // row qr:   (hA, hB, lA, lB)
        uint4 av1 = A0[8 * 4];    // row qr+8
#pragma unroll
        for (int jn = 0; jn < 8; jn++) {
            uint2 bv = B0[jn * 192];
            mma16816(acc[jn], av0.x, av1.x, av0.y, av1.y, bv.x, bv.y);  // hi
            mma16816(acc[jn], av0.z, av1.z, av0.w, av1.w, bv.x, bv.y);  // lo
        }
    }

    // ---- cross-group reduction ----
    if (grp == 1) {
#pragma unroll
        for (int jn = 0; jn < 8; jn += 2) {
            *(float4*)&red[wm][lane][jn * 4]     = *(float4*)&acc[jn][0];
            *(float4*)&red[wm][lane][jn * 4 + 4] = *(float4*)&acc[jn + 1][0];
        }
    }
    __syncthreads();
    if (grp == 1) return;

#pragma unroll
    for (int jn = 0; jn < 8; jn++) {
#pragma unroll
        for (int t = 0; t < 4; t++) acc[jn][t] += red[wm][lane][jn * 4 + t];
    }

    // ---- fused epilogue: mean-scale + biases + softmax + 2*tanh ----
    const float inv_d = 1.0f / 31.0f;
    float mx0 = -INFINITY, mx1 = -INFINITY;
#pragma unroll
    for (int jn = 0; jn < 8; jn++) {
#pragma unroll
        for (int t = 0; t < 2; t++) {
            float c = scb[jn * 8 + 2 * qc + t];
            acc[jn][t]     = acc[jn][t]     * inv_d + c;
            acc[jn][2 + t] = acc[jn][2 + t] * inv_d + c;
            mx0 = fmaxf(mx0, acc[jn][t]);
            mx1 = fmaxf(mx1, acc[jn][2 + t]);
        }
    }
    mx0 = fmaxf(mx0, __shfl_xor_sync(0xffffffffu, mx0, 1));
    mx0 = fmaxf(mx0, __shfl_xor_sync(0xffffffffu, mx0, 2));
    mx1 = fmaxf(mx1, __shfl_xor_sync(0xffffffffu, mx1, 1));
    mx1 = fmaxf(mx1, __shfl_xor_sync(0xffffffffu, mx1, 2));

    float s0 = 0.f, s1 = 0.f;
#pragma unroll
    for (int jn = 0; jn < 8; jn++) {
#pragma unroll
        for (int t = 0; t < 2; t++) {
            acc[jn][t]     = __expf(acc[jn][t] - mx0);
            acc[jn][2 + t] = __expf(acc[jn][2 + t] - mx1);
            s0 += acc[jn][t];
            s1 += acc[jn][2 + t];
        }
    }
    s0 += __shfl_xor_sync(0xffffffffu, s0, 1);
    s0 += __shfl_xor_sync(0xffffffffu, s0, 2);
    s1 += __shfl_xor_sync(0xffffffffu, s1, 1);
    s1 += __shfl_xor_sync(0xffffffffu, s1, 2);
    const float rs0 = 1.0f / s0;
    const float rs1 = 1.0f / s1;

    const int oh = c_oh[cls], ow = c_ow[cls];
    const int m0 = mw + qr;
    const int hq = m0 >> 5;
    const int wq0 = m0 & 31;
    const int ho = 2 * hq + oh;
    const int wo0 = 2 * wq0 + ow;
    const int wo1 = 2 * (wq0 + 8) + ow;
    float* obase = out + (size_t)b * COUT * (HOUT * HOUT) + (size_t)ho * HOUT;

    if (ho < HOUT) {
        const bool v0 = (wo0 < HOUT);
        const bool v1 = (wo1 < HOUT);
#pragma unroll
        for (int jn = 0; jn < 8; jn++) {
#pragma unroll
            for (int t = 0; t < 2; t++) {
                int ch = jn * 8 + 2 * qc + t;
                float* op = obase + (size_t)ch * (HOUT * HOUT);
                if (v0) {
                    float s = acc[jn][t] * rs0;
                    op[wo0] = __fdividef(4.0f, 1.0f + __expf(-2.0f * s)) - 2.0f;  // 2*tanh
                }
                if (v1) {
                    float s = acc[jn][2 + t] * rs1;
                    op[wo1] = __fdividef(4.0f, 1.0f + __expf(-2.0f * s)) - 2.0f;
                }
            }
        }
    }
}

extern "C" void kernel_launch(void* const* d_in, const int* in_sizes, int n_in,
                              void* d_out, int out_size) {
    (void)in_sizes; (void)n_in; (void)out_size;
    const float* x         = (const float*)d_in[0];
    const float* w         = (const float*)d_in[1];
    const float* conv_bias = (const float*)d_in[2];
    const float* bias      = (const float*)d_in[3];
    float* out             = (float*)d_out;

    // 512 prep blocks + ceil(9*8*6*32 / 128)=108 wc blocks
    prep_kernel<<<620, 128>>>(x, w);
    mma_fused<<<512, 256>>>(conv_bias, bias, out);
}